// round 1
// baseline (speedup 1.0000x reference)
#include <cuda_runtime.h>

#define NB 512
#define PL 200
#define QL 60
#define QE 260
#define DIM 512
#define QSTR 516          // qry smem row stride (floats), 16B aligned, conflict-friendly
#define SSTR 64           // sim smem row stride
#define DD 16             // K-chunk
#define NTHREADS 512

// smem layout (float offsets)
#define SM_QRY  0
#define SM_SIM  (QL * QSTR)            // 30960
#define SM_CTXT (SM_SIM + PL * SSTR)   // 43760
#define SM_QRYT (SM_CTXT + DD * PL)    // 46960
#define SM_M    (SM_QRYT + DD * 64)    // 47984
#define SM_WP   (SM_M + PL)            // 48184
#define SM_QV   (SM_WP + PL)           // 48384 (16B aligned)
#define SM_RED  (SM_QV + DIM)          // 48896
#define SM_TOT  (SM_RED + 64)          // 48960 floats
#define SMEM_BYTES (SM_TOT * 4)        // 195840 B

__device__ __forceinline__ float4 f4mul(float4 a, float4 b) {
    return make_float4(a.x * b.x, a.y * b.y, a.z * b.z, a.w * b.w);
}

__global__ void __launch_bounds__(NTHREADS, 1)
context_encoding_kernel(const float* __restrict__ enc, float* __restrict__ out)
{
    extern __shared__ float sm[];
    float* qry_s = sm + SM_QRY;
    float* sim_s = sm + SM_SIM;
    float* ctxT  = sm + SM_CTXT;
    float* qryT  = sm + SM_QRYT;
    float* m_arr = sm + SM_M;
    float* wp    = sm + SM_WP;
    float* qvec  = sm + SM_QV;
    float* red   = sm + SM_RED;

    const int tid  = threadIdx.x;
    const int lane = tid & 31;
    const int warp = tid >> 5;
    const int b    = blockIdx.x;

    const float* ctx_g = enc + (size_t)b * QE * DIM;
    const float* qry_g = ctx_g + PL * DIM;

    // ---- load qry (60x512) into smem, row stride 516 ----
    for (int i = tid; i < QL * DIM; i += NTHREADS) {
        int q = i >> 9;
        int d = i & (DIM - 1);
        qry_s[q * QSTR + d] = qry_g[i];
    }
    __syncthreads();

    // =============== Phase A: sim = ctx @ qry^T  (200 x 60, K=512) ===============
    const int txq = tid & 7;   // q-group: q = 8*txq + j  (q padded to 64)
    const int txp = tid >> 3;  // p-group: p = 4*txp + i
    const bool act = (txp < 50);

    float acc[4][8];
    #pragma unroll
    for (int i = 0; i < 4; i++)
        #pragma unroll
        for (int j = 0; j < 8; j++) acc[i][j] = 0.f;

    for (int d0 = 0; d0 < DIM; d0 += DD) {
        // stage ctx^T [DD][200]
        for (int i = tid; i < DD * PL; i += NTHREADS) {
            int dd = i & (DD - 1);
            int p  = i >> 4;
            ctxT[dd * PL + p] = ctx_g[p * DIM + d0 + dd];
        }
        // stage qry^T [DD][64] (zero-fill q >= 60 -> padded sim cols are exactly 0)
        {
            int q  = tid & 63;
            int dd = tid >> 6;  // 0..7
            #pragma unroll
            for (int h = 0; h < 2; h++) {
                int dd2 = dd + 8 * h;
                qryT[dd2 * 64 + q] = (q < QL) ? qry_s[q * QSTR + d0 + dd2] : 0.f;
            }
        }
        __syncthreads();
        if (act) {
            #pragma unroll
            for (int dd = 0; dd < DD; dd++) {
                float4 cv  = *(const float4*)&ctxT[dd * PL + txp * 4];
                float4 qv0 = *(const float4*)&qryT[dd * 64 + txq * 8];
                float4 qv1 = *(const float4*)&qryT[dd * 64 + txq * 8 + 4];
                float c[4]  = {cv.x, cv.y, cv.z, cv.w};
                float qq[8] = {qv0.x, qv0.y, qv0.z, qv0.w, qv1.x, qv1.y, qv1.z, qv1.w};
                #pragma unroll
                for (int i = 0; i < 4; i++)
                    #pragma unroll
                    for (int j = 0; j < 8; j++)
                        acc[i][j] += c[i] * qq[j];
            }
        }
        __syncthreads();
    }
    if (act) {
        #pragma unroll
        for (int i = 0; i < 4; i++) {
            int p = txp * 4 + i;
            #pragma unroll
            for (int j = 0; j < 8; j++)
                sim_s[p * SSTR + txq * 8 + j] = acc[i][j];
        }
    }
    __syncthreads();

    // =============== Phase B: softmax over q per p-row; record row max ===============
    for (int p = warp; p < PL; p += 16) {
        float v0 = (lane < QL)      ? sim_s[p * SSTR + lane]      : -3.4e38f;
        float v1 = (lane + 32 < QL) ? sim_s[p * SSTR + lane + 32] : -3.4e38f;
        float mx = fmaxf(v0, v1);
        #pragma unroll
        for (int o = 16; o > 0; o >>= 1)
            mx = fmaxf(mx, __shfl_xor_sync(0xffffffffu, mx, o));
        float e0 = (lane < QL)      ? expf(v0 - mx) : 0.f;
        float e1 = (lane + 32 < QL) ? expf(v1 - mx) : 0.f;
        float s = e0 + e1;
        #pragma unroll
        for (int o = 16; o > 0; o >>= 1)
            s += __shfl_xor_sync(0xffffffffu, s, o);
        float inv = 1.f / s;
        if (lane < QL)      sim_s[p * SSTR + lane]      = e0 * inv;
        if (lane + 32 < QL) sim_s[p * SSTR + lane + 32] = e1 * inv;
        if (lane == 0) m_arr[p] = mx;
    }
    __syncthreads();

    // =============== Phase C: softmax over p of max_sim -> wp[200] ===============
    {
        float v = (tid < PL) ? m_arr[tid] : -3.4e38f;
        float mv = v;
        #pragma unroll
        for (int o = 16; o > 0; o >>= 1)
            mv = fmaxf(mv, __shfl_xor_sync(0xffffffffu, mv, o));
        if (lane == 0) red[warp] = mv;
        __syncthreads();
        if (warp == 0) {
            float x = (lane < 16) ? red[lane] : -3.4e38f;
            #pragma unroll
            for (int o = 16; o > 0; o >>= 1)
                x = fmaxf(x, __shfl_xor_sync(0xffffffffu, x, o));
            if (lane == 0) red[32] = x;
        }
        __syncthreads();
        float gmax = red[32];
        float e = (tid < PL) ? expf(v - gmax) : 0.f;
        float sv = e;
        #pragma unroll
        for (int o = 16; o > 0; o >>= 1)
            sv += __shfl_xor_sync(0xffffffffu, sv, o);
        if (lane == 0) red[warp] = sv;
        __syncthreads();
        if (warp == 0) {
            float x = (lane < 16) ? red[lane] : 0.f;
            #pragma unroll
            for (int o = 16; o > 0; o >>= 1)
                x += __shfl_xor_sync(0xffffffffu, x, o);
            if (lane == 0) red[33] = x;
        }
        __syncthreads();
        if (tid < PL) wp[tid] = e / red[33];
    }
    __syncthreads();

    // =============== Phase D: q2c_vec[d] = sum_p wp[p] * ctx[p][d] ===============
    {
        float a = 0.f;
        #pragma unroll 8
        for (int p = 0; p < PL; p++)
            a += wp[p] * ctx_g[p * DIM + tid];
        qvec[tid] = a;
    }
    __syncthreads();

    // =============== Phase E: c2q = W @ qry, fused with output write ===============
    const float4* qry4 = (const float4*)qry_s;   // row stride QSTR/4 = 129
    const float4* ctx4 = (const float4*)ctx_g;   // row stride 128
    const float4* qv4  = (const float4*)qvec;
    float4* out4 = (float4*)out + (size_t)b * PL * 512;  // 2048 floats = 512 f4 per row

    for (int pp = warp; pp < PL / 2; pp += 16) {
        const int p0 = pp * 2;
        float4 a0[4], a1[4];
        #pragma unroll
        for (int j = 0; j < 4; j++) {
            a0[j] = make_float4(0.f, 0.f, 0.f, 0.f);
            a1[j] = make_float4(0.f, 0.f, 0.f, 0.f);
        }
        #pragma unroll 6
        for (int q = 0; q < QL; q++) {
            float w0 = sim_s[p0 * SSTR + q];
            float w1 = sim_s[(p0 + 1) * SSTR + q];
            #pragma unroll
            for (int j = 0; j < 4; j++) {
                float4 qv = qry4[q * (QSTR / 4) + lane + 32 * j];
                a0[j].x += w0 * qv.x; a0[j].y += w0 * qv.y;
                a0[j].z += w0 * qv.z; a0[j].w += w0 * qv.w;
                a1[j].x += w1 * qv.x; a1[j].y += w1 * qv.y;
                a1[j].z += w1 * qv.z; a1[j].w += w1 * qv.w;
            }
        }
        #pragma unroll
        for (int r = 0; r < 2; r++) {
            const int p = p0 + r;
            const size_t ob = (size_t)p * 512;
            #pragma unroll
            for (int j = 0; j < 4; j++) {
                int d4 = lane + 32 * j;
                float4 c  = ctx4[p * 128 + d4];
                float4 cq = r ? a1[j] : a0[j];
                float4 qc = qv4[d4];
                out4[ob + d4]       = c;                // ctx
                out4[ob + 128 + d4] = cq;               // c2q
                out4[ob + 256 + d4] = f4mul(c, cq);     // ctx * c2q
                out4[ob + 384 + d4] = f4mul(c, qc);     // ctx * q2c
            }
        }
    }
}

extern "C" void kernel_launch(void* const* d_in, const int* in_sizes, int n_in,
                              void* d_out, int out_size)
{
    const float* enc = (const float*)d_in[0];
    float* out = (float*)d_out;
    cudaFuncSetAttribute(context_encoding_kernel,
                         cudaFuncAttributeMaxDynamicSharedMemorySize, SMEM_BYTES);
    context_encoding_kernel<<<NB, NTHREADS, SMEM_BYTES>>>(enc, out);
}

// round 3
// speedup vs baseline: 1.9046x; 1.9046x over previous
#include <cuda_runtime.h>
#include <cuda_fp16.h>
#include <stdint.h>

#define NB 512
#define PL 200
#define QL 60
#define QE 260
#define DIM 512
#define NT 512
#define MST 36        // u32 stride of fp16-pair part arrays
#define SIMST 68      // sim fp32 row stride

// ---- smem layout (byte offsets) ----
#define SM_RED   0            // 64 f32
#define SM_MARR  256          // 256 f32
#define SM_WP    1280         // 256 f32
#define SM_QV    2304         // 512 f32
#define AW0_OFF  4608         // u32[256][36] : GEMM1 A-hi, then W-hi
#define AW1_OFF  41472        // u32[256][36] : GEMM1 A-lo, then W-lo
#define B0_OFF   78336        // u32[64][36]  : GEMM1 B-hi (qry)
#define B1_OFF   87552        // u32[64][36]  : GEMM1 B-lo
#define SIM_OFF  96768        // f32[256][68]
#define TMP_OFF  78336        // f32[64][133] (aliases B stage, dead by then)
#define QT0_OFF  112384       // u16[256][72] (aliases sim, dead by then)
#define QT1_OFF  149248       // u16[256][72]
#define SMEM_BYTES 186112

__device__ __forceinline__ uint32_t pkh(__half a, __half b) {
    return (uint32_t)__half_as_ushort(a) | ((uint32_t)__half_as_ushort(b) << 16);
}
__device__ __forceinline__ void hilo(float f, __half& h, __half& l) {
    h = __float2half_rn(f);
    l = __float2half_rn(f - __half2float(h));
}
__device__ __forceinline__ void cvt4(float4 v, uint32_t& h01, uint32_t& h23,
                                     uint32_t& l01, uint32_t& l23) {
    __half hx, hy, hz, hw, lx, ly, lz, lw;
    hilo(v.x, hx, lx); hilo(v.y, hy, ly);
    hilo(v.z, hz, lz); hilo(v.w, hw, lw);
    h01 = pkh(hx, hy); h23 = pkh(hz, hw);
    l01 = pkh(lx, ly); l23 = pkh(lz, lw);
}
__device__ __forceinline__ void mma16816(float* d, const uint32_t* a, const uint32_t* b) {
    asm volatile(
        "mma.sync.aligned.m16n8k16.row.col.f32.f16.f16.f32 "
        "{%0,%1,%2,%3}, {%4,%5,%6,%7}, {%8,%9}, {%0,%1,%2,%3};"
        : "+f"(d[0]), "+f"(d[1]), "+f"(d[2]), "+f"(d[3])
        : "r"(a[0]), "r"(a[1]), "r"(a[2]), "r"(a[3]), "r"(b[0]), "r"(b[1]));
}

__global__ void __launch_bounds__(NT, 1)
ce_hmma(const float* __restrict__ enc, float* __restrict__ out)
{
    extern __shared__ char smc[];
    float* red   = (float*)(smc + SM_RED);
    float* m_arr = (float*)(smc + SM_MARR);
    float* wp    = (float*)(smc + SM_WP);
    float* qvec  = (float*)(smc + SM_QV);
    uint32_t* AW0 = (uint32_t*)(smc + AW0_OFF);
    uint32_t* AW1 = (uint32_t*)(smc + AW1_OFF);
    uint32_t* B0s = (uint32_t*)(smc + B0_OFF);
    uint32_t* B1s = (uint32_t*)(smc + B1_OFF);
    float* sim    = (float*)(smc + SIM_OFF);
    float* tmp    = (float*)(smc + TMP_OFF);
    uint16_t* QT0 = (uint16_t*)(smc + QT0_OFF);
    uint16_t* QT1 = (uint16_t*)(smc + QT1_OFF);
    uint32_t* QT0u = (uint32_t*)(smc + QT0_OFF);
    uint32_t* QT1u = (uint32_t*)(smc + QT1_OFF);

    const int tid  = threadIdx.x;
    const int lane = tid & 31;
    const int warp = tid >> 5;
    const int b    = blockIdx.x;
    const int lq   = lane & 3;   // quad col
    const int lr   = lane >> 2;  // quad row

    const float* ctx_g = enc + (size_t)b * QE * DIM;
    const float* qry_g = ctx_g + PL * DIM;

    // ================= GEMM1: sim[256x64] = encRows @ qry^T =================
    const int wm = warp >> 1, wn = warp & 1;
    const int m0 = wm * 32, n0 = wn * 32;

    float4 pa[8], pb[2];
    {
        #pragma unroll
        for (int k = 0; k < 8; k++) {
            int idx = tid + 512 * k, r = idx >> 4, c4 = idx & 15;
            pa[k] = *(const float4*)&ctx_g[(size_t)r * DIM + c4 * 4];
        }
        #pragma unroll
        for (int k = 0; k < 2; k++) {
            int idx = tid + 512 * k, q = idx >> 4, c4 = idx & 15;
            pb[k] = (q < QL) ? *(const float4*)&qry_g[(size_t)q * DIM + c4 * 4]
                             : make_float4(0.f, 0.f, 0.f, 0.f);
        }
    }

    float acc[2][4][4];
    #pragma unroll
    for (int i = 0; i < 2; i++)
        #pragma unroll
        for (int j = 0; j < 4; j++)
            #pragma unroll
            for (int k = 0; k < 4; k++) acc[i][j][k] = 0.f;

    for (int ch = 0; ch < 8; ch++) {
        // stage from prefetched regs
        #pragma unroll
        for (int k = 0; k < 8; k++) {
            int idx = tid + 512 * k, r = idx >> 4, c4 = idx & 15;
            uint32_t h01, h23, l01, l23;
            cvt4(pa[k], h01, h23, l01, l23);
            int o = r * MST + c4 * 2;
            AW0[o] = h01; AW0[o + 1] = h23;
            AW1[o] = l01; AW1[o + 1] = l23;
        }
        #pragma unroll
        for (int k = 0; k < 2; k++) {
            int idx = tid + 512 * k, q = idx >> 4, c4 = idx & 15;
            uint32_t h01, h23, l01, l23;
            cvt4(pb[k], h01, h23, l01, l23);
            int o = q * MST + c4 * 2;
            B0s[o] = h01; B0s[o + 1] = h23;
            B1s[o] = l01; B1s[o + 1] = l23;
        }
        __syncthreads();

        if (ch < 7) {  // prefetch next chunk; LDG latency hides under MMA
            const int d0 = (ch + 1) * 64;
            #pragma unroll
            for (int k = 0; k < 8; k++) {
                int idx = tid + 512 * k, r = idx >> 4, c4 = idx & 15;
                pa[k] = *(const float4*)&ctx_g[(size_t)r * DIM + d0 + c4 * 4];
            }
            #pragma unroll
            for (int k = 0; k < 2; k++) {
                int idx = tid + 512 * k, q = idx >> 4, c4 = idx & 15;
                pb[k] = (q < QL) ? *(const float4*)&qry_g[(size_t)q * DIM + d0 + c4 * 4]
                                 : make_float4(0.f, 0.f, 0.f, 0.f);
            }
        }

        #pragma unroll
        for (int ks = 0; ks < 4; ks++) {
            const int kc = ks * 8 + lq;
            uint32_t bh[4][2], bl[4][2];
            #pragma unroll
            for (int nt = 0; nt < 4; nt++) {
                int br = (n0 + nt * 8 + lr) * MST + kc;
                bh[nt][0] = B0s[br]; bh[nt][1] = B0s[br + 4];
                bl[nt][0] = B1s[br]; bl[nt][1] = B1s[br + 4];
            }
            #pragma unroll
            for (int mt = 0; mt < 2; mt++) {
                int ar = (m0 + mt * 16 + lr) * MST + kc, ar8 = ar + 8 * MST;
                uint32_t ah[4] = {AW0[ar], AW0[ar8], AW0[ar + 4], AW0[ar8 + 4]};
                uint32_t al[4] = {AW1[ar], AW1[ar8], AW1[ar + 4], AW1[ar8 + 4]};
                #pragma unroll
                for (int nt = 0; nt < 4; nt++) {
                    mma16816(acc[mt][nt], ah, bh[nt]);
                    mma16816(acc[mt][nt], ah, bl[nt]);
                    mma16816(acc[mt][nt], al, bh[nt]);
                }
            }
        }
        __syncthreads();
    }

    // write sim to smem
    #pragma unroll
    for (int mt = 0; mt < 2; mt++) {
        int r = m0 + mt * 16 + lr;
        #pragma unroll
        for (int nt = 0; nt < 4; nt++) {
            int c = n0 + nt * 8 + lq * 2;
            *(float2*)&sim[r * SIMST + c]       = make_float2(acc[mt][nt][0], acc[mt][nt][1]);
            *(float2*)&sim[(r + 8) * SIMST + c] = make_float2(acc[mt][nt][2], acc[mt][nt][3]);
        }
    }
    __syncthreads();

    // ====== softmax over q per row; write W as fp16 hi/lo pairs into AW0/AW1 ======
    for (int p = warp; p < 256; p += 16) {
        float v0 = (lane < QL)      ? sim[p * SIMST + lane]      : -3.4e38f;
        float v1 = (lane + 32 < QL) ? sim[p * SIMST + lane + 32] : -3.4e38f;
        float mx = fmaxf(v0, v1);
        #pragma unroll
        for (int o = 16; o > 0; o >>= 1)
            mx = fmaxf(mx, __shfl_xor_sync(0xffffffffu, mx, o));
        float e0 = (lane < QL)      ? expf(v0 - mx) : 0.f;
        float e1 = (lane + 32 < QL) ? expf(v1 - mx) : 0.f;
        float s = e0 + e1;
        #pragma unroll
        for (int o = 16; o > 0; o >>= 1)
            s += __shfl_xor_sync(0xffffffffu, s, o);
        float inv = 1.f / s;
        float w0 = e0 * inv, w1 = e1 * inv;
        if (lane == 0) m_arr[p] = mx;

        __half h, l;
        hilo(w0, h, l);
        uint32_t c0 = (uint32_t)__half_as_ushort(h) | ((uint32_t)__half_as_ushort(l) << 16);
        uint32_t o0 = __shfl_down_sync(0xffffffffu, c0, 1);
        hilo(w1, h, l);
        uint32_t c1 = (uint32_t)__half_as_ushort(h) | ((uint32_t)__half_as_ushort(l) << 16);
        uint32_t o1 = __shfl_down_sync(0xffffffffu, c1, 1);
        if (!(lane & 1)) {
            int base = p * MST + (lane >> 1);
            AW0[base]      = (c0 & 0xffffu) | (o0 << 16);
            AW1[base]      = (c0 >> 16)     | (o0 & 0xffff0000u);
            AW0[base + 16] = (c1 & 0xffffu) | (o1 << 16);
            AW1[base + 16] = (c1 >> 16)     | (o1 & 0xffff0000u);
        }
    }
    __syncthreads();

    // ====== softmax over p of max_sim -> wp[200] ======
    {
        float v = (tid < PL) ? m_arr[tid] : -3.4e38f;
        float mv = v;
        #pragma unroll
        for (int o = 16; o > 0; o >>= 1) mv = fmaxf(mv, __shfl_xor_sync(0xffffffffu, mv, o));
        if (lane == 0) red[warp] = mv;
        __syncthreads();
        if (warp == 0) {
            float x = (lane < 16) ? red[lane] : -3.4e38f;
            #pragma unroll
            for (int o = 16; o > 0; o >>= 1) x = fmaxf(x, __shfl_xor_sync(0xffffffffu, x, o));
            if (lane == 0) red[32] = x;
        }
        __syncthreads();
        float gmax = red[32];
        float e = (tid < PL) ? expf(v - gmax) : 0.f;
        float sv = e;
        #pragma unroll
        for (int o = 16; o > 0; o >>= 1) sv += __shfl_xor_sync(0xffffffffu, sv, o);
        if (lane == 0) red[warp] = sv;
        __syncthreads();
        if (warp == 0) {
            float x = (lane < 16) ? red[lane] : 0.f;
            #pragma unroll
            for (int o = 16; o > 0; o >>= 1) x += __shfl_xor_sync(0xffffffffu, x, o);
            if (lane == 0) red[33] = x;
        }
        __syncthreads();
        if (tid < PL) wp[tid] = e / red[33];
    }
    __syncthreads();

    // ====== q2c_vec[d] = sum_p wp[p] * ctx[p][d] ======
    {
        float a = 0.f;
        #pragma unroll 8
        for (int p = 0; p < PL; p++) a += wp[p] * ctx_g[(size_t)p * DIM + tid];
        qvec[tid] = a;
    }
    __syncthreads();

    // ================= GEMM2: c2q = W @ qry + fused epilogue =================
    const int wm2 = warp >> 2, wn2 = warp & 3;

    for (int half = 0; half < 2; half++) {
        // ---- build qry^T fp16 hi/lo for d in [half*256, half*256+256) ----
        for (int tch = 0; tch < 2; tch++) {
            const int dbase = half * 256 + tch * 128;
            #pragma unroll
            for (int i = 0; i < 4; i++) {
                int idx = tid + 512 * i, q = idx >> 5, c4 = idx & 31;
                float4 v = (q < QL) ? *(const float4*)&qry_g[(size_t)q * DIM + dbase + c4 * 4]
                                    : make_float4(0.f, 0.f, 0.f, 0.f);
                int o = q * 133 + c4 * 4;
                tmp[o] = v.x; tmp[o + 1] = v.y; tmp[o + 2] = v.z; tmp[o + 3] = v.w;
            }
            __syncthreads();
            {
                const int dl = tid >> 2;
                const int qb = (tid & 3) * 16;
                const int drow = tch * 128 + dl;
                #pragma unroll
                for (int j = 0; j < 16; j++) {
                    int q = qb + j;
                    float f = tmp[q * 133 + dl];
                    __half h, l;
                    hilo(f, h, l);
                    QT0[drow * 72 + q] = __half_as_ushort(h);
                    QT1[drow * 72 + q] = __half_as_ushort(l);
                }
            }
            __syncthreads();
        }

        for (int dch = 0; dch < 2; dch++) {
            float a2[4][4][4];
            #pragma unroll
            for (int i = 0; i < 4; i++)
                #pragma unroll
                for (int j = 0; j < 4; j++)
                    #pragma unroll
                    for (int k = 0; k < 4; k++) a2[i][j][k] = 0.f;

            #pragma unroll
            for (int ks = 0; ks < 4; ks++) {
                const int kc = ks * 8 + lq;
                uint32_t bh[4][2], bl[4][2];
                #pragma unroll
                for (int nt = 0; nt < 4; nt++) {
                    int br = (dch * 128 + wn2 * 32 + nt * 8 + lr) * MST + kc;
                    bh[nt][0] = QT0u[br]; bh[nt][1] = QT0u[br + 4];
                    bl[nt][0] = QT1u[br]; bl[nt][1] = QT1u[br + 4];
                }
                #pragma unroll
                for (int mt = 0; mt < 4; mt++) {
                    int ar = (wm2 * 64 + mt * 16 + lr) * MST + kc, ar8 = ar + 8 * MST;
                    uint32_t ah[4] = {AW0[ar], AW0[ar8], AW0[ar + 4], AW0[ar8 + 4]};
                    uint32_t al[4] = {AW1[ar], AW1[ar8], AW1[ar + 4], AW1[ar8 + 4]};
                    #pragma unroll
                    for (int nt = 0; nt < 4; nt++) {
                        mma16816(a2[mt][nt], ah, bh[nt]);
                        mma16816(a2[mt][nt], ah, bl[nt]);
                        mma16816(a2[mt][nt], al, bh[nt]);
                    }
                }
            }

            // fused epilogue: write 4 output segments for this 128-d chunk
            const int dbase2 = half * 256 + dch * 128 + wn2 * 32;
            #pragma unroll
            for (int mt = 0; mt < 4; mt++) {
                #pragma unroll
                for (int rh = 0; rh < 2; rh++) {
                    int p = wm2 * 64 + mt * 16 + lr + rh * 8;
                    if (p < PL) {
                        float2* ob = (float2*)out + ((size_t)b * PL + p) * 1024;
                        const float2* cg = (const float2*)(ctx_g + (size_t)p * DIM);
                        #pragma unroll
                        for (int nt = 0; nt < 4; nt++) {
                            int d = dbase2 + nt * 8 + lq * 2;
                            int d2 = d >> 1;
                            float2 c  = cg[d2];
                            float2 cq = make_float2(a2[mt][nt][rh * 2], a2[mt][nt][rh * 2 + 1]);
                            float2 qc = *(float2*)&qvec[d];
                            ob[d2]       = c;
                            ob[256 + d2] = cq;
                            ob[512 + d2] = make_float2(c.x * cq.x, c.y * cq.y);
                            ob[768 + d2] = make_float2(c.x * qc.x, c.y * qc.y);
                        }
                    }
                }
            }
        }
        __syncthreads();
    }
}

extern "C" void kernel_launch(void* const* d_in, const int* in_sizes, int n_in,
                              void* d_out, int out_size)
{
    const float* enc = (const float*)d_in[0];
    float* out = (float*)d_out;
    cudaFuncSetAttribute(ce_hmma,
                         cudaFuncAttributeMaxDynamicSharedMemorySize, SMEM_BYTES);
    ce_hmma<<<NB, NT, SMEM_BYTES>>>(enc, out);
}

// round 4
// speedup vs baseline: 2.0874x; 1.0960x over previous
#include <cuda_runtime.h>
#include <cuda_fp16.h>
#include <stdint.h>

#define NB 512
#define PL 200
#define QL 60
#define QE 260
#define DIM 512
#define NT 512
#define MST 36        // u32 stride of fp16-pair part arrays
#define EPST 132      // epilogue bounce buffer f32 stride

// ---- smem layout (byte offsets) ----
#define SM_RED   0            // 64 f32
#define SM_MARR  256          // 256 f32
#define SM_WP    1280         // 256 f32
#define SM_QV    2304         // 512 f32
#define SM_PMAX  4352         // 512 f32
#define SM_PSUM  6400         // 512 f32
#define AW0_OFF  8448         // u32[256][36] : GEMM1 A-hi -> W-hi
#define AW1_OFF  45312        // u32[256][36] : GEMM1 A-lo -> W-lo
#define QT0_OFF  82176        // u16[256][72] : qry^T hi
#define QT1_OFF  119040       // u16[256][72] : qry^T lo
#define EPB_OFF  155904       // f32[128][132] bounce; aliases B stage + tmp
#define B0_OFF   EPB_OFF              // u32[64][36]
#define B1_OFF   (EPB_OFF + 9216)     // u32[64][36]
#define TMP_OFF  EPB_OFF              // f32[64][133]
#define SMEM_BYTES (EPB_OFF + 128 * EPST * 4)   // 223488

__device__ __forceinline__ uint32_t pkh(__half a, __half b) {
    return (uint32_t)__half_as_ushort(a) | ((uint32_t)__half_as_ushort(b) << 16);
}
__device__ __forceinline__ void hilo(float f, __half& h, __half& l) {
    h = __float2half_rn(f);
    l = __float2half_rn(f - __half2float(h));
}
__device__ __forceinline__ void cvt4(float4 v, uint32_t& h01, uint32_t& h23,
                                     uint32_t& l01, uint32_t& l23) {
    __half hx, hy, hz, hw, lx, ly, lz, lw;
    hilo(v.x, hx, lx); hilo(v.y, hy, ly);
    hilo(v.z, hz, lz); hilo(v.w, hw, lw);
    h01 = pkh(hx, hy); h23 = pkh(hz, hw);
    l01 = pkh(lx, ly); l23 = pkh(lz, lw);
}
__device__ __forceinline__ void mma16816(float* d, const uint32_t* a, const uint32_t* b) {
    asm volatile(
        "mma.sync.aligned.m16n8k16.row.col.f32.f16.f16.f32 "
        "{%0,%1,%2,%3}, {%4,%5,%6,%7}, {%8,%9}, {%0,%1,%2,%3};"
        : "+f"(d[0]), "+f"(d[1]), "+f"(d[2]), "+f"(d[3])
        : "r"(a[0]), "r"(a[1]), "r"(a[2]), "r"(a[3]), "r"(b[0]), "r"(b[1]));
}

__global__ void __launch_bounds__(NT, 1)
ce_hmma2(const float* __restrict__ enc, float* __restrict__ out)
{
    extern __shared__ char smc[];
    float* red   = (float*)(smc + SM_RED);
    float* m_arr = (float*)(smc + SM_MARR);
    float* wp    = (float*)(smc + SM_WP);
    float* qvec  = (float*)(smc + SM_QV);
    float* pmax  = (float*)(smc + SM_PMAX);
    float* psum  = (float*)(smc + SM_PSUM);
    uint32_t* AW0 = (uint32_t*)(smc + AW0_OFF);
    uint32_t* AW1 = (uint32_t*)(smc + AW1_OFF);
    uint32_t* B0s = (uint32_t*)(smc + B0_OFF);
    uint32_t* B1s = (uint32_t*)(smc + B1_OFF);
    uint32_t* QT0u = (uint32_t*)(smc + QT0_OFF);
    uint32_t* QT1u = (uint32_t*)(smc + QT1_OFF);
    float* tmp   = (float*)(smc + TMP_OFF);
    float* EP    = (float*)(smc + EPB_OFF);

    const int tid  = threadIdx.x;
    const int lane = tid & 31;
    const int warp = tid >> 5;
    const int b    = blockIdx.x;
    const int lq   = lane & 3;
    const int lr   = lane >> 2;

    const float* ctx_g = enc + (size_t)b * QE * DIM;
    const float* qry_g = ctx_g + PL * DIM;

    // ================= GEMM1: sim[256x64] = encRows @ qry^T =================
    const int wm = warp >> 1, wn = warp & 1;
    const int m0 = wm * 32, n0 = wn * 32;

    float4 pa[8], pb[2];
    {
        #pragma unroll
        for (int k = 0; k < 8; k++) {
            int idx = tid + 512 * k, r = idx >> 4, c4 = idx & 15;
            pa[k] = *(const float4*)&ctx_g[(size_t)r * DIM + c4 * 4];
        }
        #pragma unroll
        for (int k = 0; k < 2; k++) {
            int idx = tid + 512 * k, q = idx >> 4, c4 = idx & 15;
            pb[k] = (q < QL) ? *(const float4*)&qry_g[(size_t)q * DIM + c4 * 4]
                             : make_float4(0.f, 0.f, 0.f, 0.f);
        }
    }

    float acc[2][4][4];
    #pragma unroll
    for (int i = 0; i < 2; i++)
        #pragma unroll
        for (int j = 0; j < 4; j++)
            #pragma unroll
            for (int k = 0; k < 4; k++) acc[i][j][k] = 0.f;

    for (int ch = 0; ch < 8; ch++) {
        #pragma unroll
        for (int k = 0; k < 8; k++) {
            int idx = tid + 512 * k, r = idx >> 4, c4 = idx & 15;
            uint32_t h01, h23, l01, l23;
            cvt4(pa[k], h01, h23, l01, l23);
            int o = r * MST + c4 * 2;
            AW0[o] = h01; AW0[o + 1] = h23;
            AW1[o] = l01; AW1[o + 1] = l23;
        }
        #pragma unroll
        for (int k = 0; k < 2; k++) {
            int idx = tid + 512 * k, q = idx >> 4, c4 = idx & 15;
            uint32_t h01, h23, l01, l23;
            cvt4(pb[k], h01, h23, l01, l23);
            int o = q * MST + c4 * 2;
            B0s[o] = h01; B0s[o + 1] = h23;
            B1s[o] = l01; B1s[o + 1] = l23;
        }
        __syncthreads();

        if (ch < 7) {
            const int d0 = (ch + 1) * 64;
            #pragma unroll
            for (int k = 0; k < 8; k++) {
                int idx = tid + 512 * k, r = idx >> 4, c4 = idx & 15;
                pa[k] = *(const float4*)&ctx_g[(size_t)r * DIM + d0 + c4 * 4];
            }
            #pragma unroll
            for (int k = 0; k < 2; k++) {
                int idx = tid + 512 * k, q = idx >> 4, c4 = idx & 15;
                pb[k] = (q < QL) ? *(const float4*)&qry_g[(size_t)q * DIM + d0 + c4 * 4]
                                 : make_float4(0.f, 0.f, 0.f, 0.f);
            }
        }

        #pragma unroll
        for (int ks = 0; ks < 4; ks++) {
            const int kc = ks * 8 + lq;
            uint32_t bh[4][2], bl[4][2];
            #pragma unroll
            for (int nt = 0; nt < 4; nt++) {
                int br = (n0 + nt * 8 + lr) * MST + kc;
                bh[nt][0] = B0s[br]; bh[nt][1] = B0s[br + 4];
                bl[nt][0] = B1s[br]; bl[nt][1] = B1s[br + 4];
            }
            #pragma unroll
            for (int mt = 0; mt < 2; mt++) {
                int ar = (m0 + mt * 16 + lr) * MST + kc, ar8 = ar + 8 * MST;
                uint32_t ah[4] = {AW0[ar], AW0[ar8], AW0[ar + 4], AW0[ar8 + 4]};
                uint32_t al[4] = {AW1[ar], AW1[ar8], AW1[ar + 4], AW1[ar8 + 4]};
                #pragma unroll
                for (int nt = 0; nt < 4; nt++) {
                    mma16816(acc[mt][nt], ah, bh[nt]);
                    mma16816(acc[mt][nt], ah, bl[nt]);
                    mma16816(acc[mt][nt], al, bh[nt]);
                }
            }
        }
        __syncthreads();
    }

    // ====== fragment-resident softmax over q; W -> AW0/AW1 as fp16 hi/lo ======
    {
        // local max (masked cols >= QL)
        float mx[2][2];
        #pragma unroll
        for (int mt = 0; mt < 2; mt++) { mx[mt][0] = -3.4e38f; mx[mt][1] = -3.4e38f; }
        #pragma unroll
        for (int mt = 0; mt < 2; mt++)
            #pragma unroll
            for (int nt = 0; nt < 4; nt++) {
                int col = n0 + nt * 8 + lq * 2;
                if (col < QL) {
                    mx[mt][0] = fmaxf(mx[mt][0], acc[mt][nt][0]);
                    mx[mt][1] = fmaxf(mx[mt][1], acc[mt][nt][2]);
                }
                if (col + 1 < QL) {
                    mx[mt][0] = fmaxf(mx[mt][0], acc[mt][nt][1]);
                    mx[mt][1] = fmaxf(mx[mt][1], acc[mt][nt][3]);
                }
            }
        #pragma unroll
        for (int mt = 0; mt < 2; mt++)
            #pragma unroll
            for (int rh = 0; rh < 2; rh++) {
                mx[mt][rh] = fmaxf(mx[mt][rh], __shfl_xor_sync(0xffffffffu, mx[mt][rh], 1));
                mx[mt][rh] = fmaxf(mx[mt][rh], __shfl_xor_sync(0xffffffffu, mx[mt][rh], 2));
            }
        if (lq == 0) {
            #pragma unroll
            for (int mt = 0; mt < 2; mt++)
                #pragma unroll
                for (int rh = 0; rh < 2; rh++)
                    pmax[wn * 256 + m0 + mt * 16 + rh * 8 + lr] = mx[mt][rh];
        }
        __syncthreads();
        float fmx[2][2];
        #pragma unroll
        for (int mt = 0; mt < 2; mt++)
            #pragma unroll
            for (int rh = 0; rh < 2; rh++) {
                int row = m0 + mt * 16 + rh * 8 + lr;
                fmx[mt][rh] = fmaxf(pmax[row], pmax[256 + row]);
                if (wn == 0 && lq == 0) m_arr[row] = fmx[mt][rh];
            }
        // exp + local sums (overwrite acc with e)
        float sm[2][2];
        #pragma unroll
        for (int mt = 0; mt < 2; mt++) { sm[mt][0] = 0.f; sm[mt][1] = 0.f; }
        #pragma unroll
        for (int mt = 0; mt < 2; mt++)
            #pragma unroll
            for (int nt = 0; nt < 4; nt++) {
                int col = n0 + nt * 8 + lq * 2;
                float e0 = (col     < QL) ? expf(acc[mt][nt][0] - fmx[mt][0]) : 0.f;
                float e1 = (col + 1 < QL) ? expf(acc[mt][nt][1] - fmx[mt][0]) : 0.f;
                float e2 = (col     < QL) ? expf(acc[mt][nt][2] - fmx[mt][1]) : 0.f;
                float e3 = (col + 1 < QL) ? expf(acc[mt][nt][3] - fmx[mt][1]) : 0.f;
                acc[mt][nt][0] = e0; acc[mt][nt][1] = e1;
                acc[mt][nt][2] = e2; acc[mt][nt][3] = e3;
                sm[mt][0] += e0 + e1; sm[mt][1] += e2 + e3;
            }
        #pragma unroll
        for (int mt = 0; mt < 2; mt++)
            #pragma unroll
            for (int rh = 0; rh < 2; rh++) {
                sm[mt][rh] += __shfl_xor_sync(0xffffffffu, sm[mt][rh], 1);
                sm[mt][rh] += __shfl_xor_sync(0xffffffffu, sm[mt][rh], 2);
            }
        if (lq == 0) {
            #pragma unroll
            for (int mt = 0; mt < 2; mt++)
                #pragma unroll
                for (int rh = 0; rh < 2; rh++)
                    psum[wn * 256 + m0 + mt * 16 + rh * 8 + lr] = sm[mt][rh];
        }
        __syncthreads();
        #pragma unroll
        for (int mt = 0; mt < 2; mt++) {
            float inv0, inv1;
            {
                int r0 = m0 + mt * 16 + lr;
                inv0 = 1.f / (psum[r0] + psum[256 + r0]);
                inv1 = 1.f / (psum[r0 + 8] + psum[256 + r0 + 8]);
            }
            #pragma unroll
            for (int nt = 0; nt < 4; nt++) {
                int cw = wn * 16 + nt * 4 + lq;      // u32 col index
                int r0 = (m0 + mt * 16 + lr) * MST;
                int r1 = r0 + 8 * MST;
                __half h0, l0, h1, l1;
                hilo(acc[mt][nt][0] * inv0, h0, l0);
                hilo(acc[mt][nt][1] * inv0, h1, l1);
                AW0[r0 + cw] = pkh(h0, h1);
                AW1[r0 + cw] = pkh(l0, l1);
                hilo(acc[mt][nt][2] * inv1, h0, l0);
                hilo(acc[mt][nt][3] * inv1, h1, l1);
                AW0[r1 + cw] = pkh(h0, h1);
                AW1[r1 + cw] = pkh(l0, l1);
            }
        }
    }
    __syncthreads();

    // ====== softmax over p of max_sim -> wp[200] ======
    {
        float v = (tid < PL) ? m_arr[tid] : -3.4e38f;
        float mv = v;
        #pragma unroll
        for (int o = 16; o > 0; o >>= 1) mv = fmaxf(mv, __shfl_xor_sync(0xffffffffu, mv, o));
        if (lane == 0) red[warp] = mv;
        __syncthreads();
        if (warp == 0) {
            float x = (lane < 16) ? red[lane] : -3.4e38f;
            #pragma unroll
            for (int o = 16; o > 0; o >>= 1) x = fmaxf(x, __shfl_xor_sync(0xffffffffu, x, o));
            if (lane == 0) red[32] = x;
        }
        __syncthreads();
        float gmax = red[32];
        float e = (tid < PL) ? expf(v - gmax) : 0.f;
        float sv = e;
        #pragma unroll
        for (int o = 16; o > 0; o >>= 1) sv += __shfl_xor_sync(0xffffffffu, sv, o);
        if (lane == 0) red[warp] = sv;
        __syncthreads();
        if (warp == 0) {
            float x = (lane < 16) ? red[lane] : 0.f;
            #pragma unroll
            for (int o = 16; o > 0; o >>= 1) x += __shfl_xor_sync(0xffffffffu, x, o);
            if (lane == 0) red[33] = x;
        }
        __syncthreads();
        if (tid < PL) wp[tid] = e / red[33];
    }
    __syncthreads();

    // ====== q2c_vec[d] = sum_p wp[p] * ctx[p][d] ======
    {
        float a = 0.f;
        #pragma unroll 8
        for (int p = 0; p < PL; p++) a += wp[p] * ctx_g[(size_t)p * DIM + tid];
        qvec[tid] = a;
    }

    // ================= GEMM2: c2q = W @ qry + coalesced epilogue =================
    const int wm2 = warp >> 2, wn2 = warp & 3;
    const float4* ctx4 = (const float4*)ctx_g;
    const float4* qv4  = (const float4*)qvec;
    float4* out4 = (float4*)out + (size_t)b * PL * 512;

    for (int half = 0; half < 2; half++) {
        __syncthreads();   // protect tmp region (prev EP readers / B stage / qvec done)

        // ---- build qry^T fp16 hi/lo for d in [half*256, half*256+256) ----
        for (int tch = 0; tch < 2; tch++) {
            const int dbase = half * 256 + tch * 128;
            #pragma unroll
            for (int i = 0; i < 4; i++) {
                int idx = tid + 512 * i, q = idx >> 5, c4 = idx & 31;
                float4 v = (q < QL) ? *(const float4*)&qry_g[(size_t)q * DIM + dbase + c4 * 4]
                                    : make_float4(0.f, 0.f, 0.f, 0.f);
                int o = q * 133 + c4 * 4;
                tmp[o] = v.x; tmp[o + 1] = v.y; tmp[o + 2] = v.z; tmp[o + 3] = v.w;
            }
            __syncthreads();
            {
                const int dl = tid >> 2;
                const int qb = (tid & 3) * 16;
                const int drow = tch * 128 + dl;
                #pragma unroll
                for (int j = 0; j < 16; j += 2) {
                    float f0 = tmp[(qb + j) * 133 + dl];
                    float f1 = tmp[(qb + j + 1) * 133 + dl];
                    __half h0, l0, h1, l1;
                    hilo(f0, h0, l0); hilo(f1, h1, l1);
                    int o = drow * MST + ((qb + j) >> 1);
                    QT0u[o] = pkh(h0, h1);
                    QT1u[o] = pkh(l0, l1);
                }
            }
            __syncthreads();
        }

        for (int dch = 0; dch < 2; dch++) {
            float a2[4][4][4];
            #pragma unroll
            for (int i = 0; i < 4; i++)
                #pragma unroll
                for (int j = 0; j < 4; j++)
                    #pragma unroll
                    for (int k = 0; k < 4; k++) a2[i][j][k] = 0.f;

            #pragma unroll
            for (int ks = 0; ks < 4; ks++) {
                const int kc = ks * 8 + lq;
                uint32_t bh[4][2], bl[4][2];
                #pragma unroll
                for (int nt = 0; nt < 4; nt++) {
                    int br = (dch * 128 + wn2 * 32 + nt * 8 + lr) * MST + kc;
                    bh[nt][0] = QT0u[br]; bh[nt][1] = QT0u[br + 4];
                    bl[nt][0] = QT1u[br]; bl[nt][1] = QT1u[br + 4];
                }
                #pragma unroll
                for (int mt = 0; mt < 4; mt++) {
                    int ar = (wm2 * 64 + mt * 16 + lr) * MST + kc, ar8 = ar + 8 * MST;
                    uint32_t ah[4] = {AW0[ar], AW0[ar8], AW0[ar + 4], AW0[ar8 + 4]};
                    uint32_t al[4] = {AW1[ar], AW1[ar8], AW1[ar + 4], AW1[ar8 + 4]};
                    #pragma unroll
                    for (int nt = 0; nt < 4; nt++) {
                        mma16816(a2[mt][nt], ah, bh[nt]);
                        mma16816(a2[mt][nt], ah, bl[nt]);
                        mma16816(a2[mt][nt], al, bh[nt]);
                    }
                }
            }

            // ---- epilogue: 2 units of 128 p-rows bounced through smem ----
            for (int mtg = 0; mtg < 2; mtg++) {
                __syncthreads();   // EP region free
                #pragma unroll
                for (int m2 = 0; m2 < 2; m2++) {
                    const int mt = mtg * 2 + m2;
                    const int er = wm2 * 32 + m2 * 16 + lr;
                    #pragma unroll
                    for (int nt = 0; nt < 4; nt++) {
                        int col = wn2 * 32 + nt * 8 + lq * 2;
                        *(float2*)&EP[er * EPST + col] =
                            make_float2(a2[mt][nt][0], a2[mt][nt][1]);
                        *(float2*)&EP[(er + 8) * EPST + col] =
                            make_float2(a2[mt][nt][2], a2[mt][nt][3]);
                    }
                }
                __syncthreads();
                #pragma unroll
                for (int pass = 0; pass < 2; pass++) {
                    const int er = pass * 64 + (tid >> 3);
                    const int p  = (er >> 5) * 64 + mtg * 32 + (er & 31);
                    if (p < PL) {
                        const int cbase = (tid & 7) * 4;
                        const int dbase = half * 256 + dch * 128;
                        float4 c4v[4];
                        #pragma unroll
                        for (int j = 0; j < 4; j++)
                            c4v[j] = ctx4[(size_t)p * 128 + ((dbase + cbase + 32 * j) >> 2)];
                        #pragma unroll
                        for (int j = 0; j < 4; j++) {
                            int d = dbase + cbase + 32 * j;
                            float4 cq = *(float4*)&EP[er * EPST + cbase + 32 * j];
                            float4 qc = qv4[d >> 2];
                            float4 c  = c4v[j];
                            float4* obase = out4 + (size_t)p * 512 + (d >> 2);
                            __stcs(obase,       c);
                            __stcs(obase + 128, cq);
                            __stcs(obase + 256, make_float4(c.x * cq.x, c.y * cq.y,
                                                            c.z * cq.z, c.w * cq.w));
                            __stcs(obase + 384, make_float4(c.x * qc.x, c.y * qc.y,
                                                            c.z * qc.z, c.w * qc.w));
                        }
                    }
                }
            }
        }
    }
}

extern "C" void kernel_launch(void* const* d_in, const int* in_sizes, int n_in,
                              void* d_out, int out_size)
{
    const float* enc = (const float*)d_in[0];
    float* out = (float*)d_out;
    cudaFuncSetAttribute(ce_hmma2,
                         cudaFuncAttributeMaxDynamicSharedMemorySize, SMEM_BYTES);
    ce_hmma2<<<NB, NT, SMEM_BYTES>>>(enc, out);
}